// round 9
// baseline (speedup 1.0000x reference)
#include <cuda_runtime.h>
#include <math.h>

// Problem constants
#define TT    4096
#define BB    32
#define HH    512
#define HB    (HH * BB)            // 16384 floats per step
#define NCTA  128                  // persistent CTAs, all wave-1 resident
#define UNITS 4                    // hidden units per CTA
#define ROWS  16                   // gate rows per CTA (4 gates x 4 units)
#define NTHR  512                  // 16 warps
#define NSEG  16                   // k-segments per row (one per warp)

// Sentinel: -NaN bit pattern. h = o*tanh(c) can never produce it.
#define NANP 0xFFF00000FFF00000ULL

// Dynamic SMEM layout (floats)
#define PART_FLOATS (ROWS * NSEG * BB)          // 8192 floats = 32KB per buffer
#define SMEM_W2     (HH * ROWS * 2)             // duplicated weights: 64KB
#define SMEM_FLOATS (SMEM_W2 + 2 * PART_FLOATS + 128)
#define SMEM_BYTES  (SMEM_FLOATS * 4)           // ~131.5KB

// Inter-step hidden state [t][j][b] (b fastest). Distinct buffer per step,
// each location written EXACTLY once per replay => the data itself is the
// flag: pre-filled with NANP; a consumer load sees sentinel (retry) or the
// final value. No flags, no REDs, no fences. Producers never wait on
// consumers -> deadlock impossible; STG->L2 visibility proven in R5/R8.
__device__ float g_h[(size_t)TT * HB];   // 256 MB static scratch

// NaN-fill all of g_h each replay (~45us, stream-ordered before lstm).
__global__ void __launch_bounds__(1024)
fill_kernel() {
    size_t i = (size_t)blockIdx.x * blockDim.x + threadIdx.x;
    ((ulonglong2*)g_h)[i] = make_ulonglong2(NANP, NANP);
}

// Packed f32x2 FMA (Blackwell packed fp32 pipe).
__device__ __forceinline__ void fma2(unsigned long long& d,
                                     unsigned long long a,
                                     unsigned long long b) {
    asm("fma.rn.f32x2 %0, %1, %2, %0;" : "+l"(d) : "l"(a), "l"(b));
}
// Acquire 64-bit load (proven spin primitive from R5/R8 poll loops).
__device__ __forceinline__ void ld_acq64(unsigned long long& v,
                                         const unsigned long long* p) {
    asm volatile("ld.acquire.gpu.global.u64 %0, [%1];"
                 : "=l"(v) : "l"(p) : "memory");
}

// Sigmoid via __expf is safe (R2/R4/R5/R8 evidence). tanh MUST stay accurate
// tanhf (R3: approx tanh -> rel_err 7e-4, too close to the 1e-3 gate).
__device__ __forceinline__ float sig_f(float x) {
    return __fdividef(1.0f, 1.0f + __expf(-x));
}

__global__ void __launch_bounds__(NTHR, 1)
lstm_kernel(const float* __restrict__ x0,     // (T,B,1)
            const float* __restrict__ W_ih,   // (4H,1)
            const float* __restrict__ W_hh,   // (4H,H) row-major
            const float* __restrict__ b_ih,   // (4H)
            const float* __restrict__ b_hh)   // (4H)
{
    extern __shared__ float sm[];
    float* W2   = sm;                        // [k][r] duplicated pairs
    float* part = sm + SMEM_W2;              // 2 x [r][seg][b]
    float* x0s  = part + 2 * PART_FLOATS;    // 2 x 32 (double-buffered)
    float* wih  = x0s + 64;                  // 16
    float* bsum = wih + 16;                  // 16

    const int tid  = threadIdx.x;
    const int lane = tid & 31;
    const int w    = tid >> 5;           // warp 0..15 = k-segment
    const int kh   = lane >> 4;          // row-half: rows 8*kh .. 8*kh+7
    const int p    = lane & 15;          // batch pair -> batches 2p, 2p+1
    const int kbeg = w * 32;             // 32 k's per warp
    const int j0   = blockIdx.x * UNITS;

    // Stage W_hh slice, k-major, duplicated pairs: W2[(k*16+r)*2 + {0,1}] = w.
    for (int idx = tid; idx < ROWS * HH; idx += NTHR) {
        int r = idx & 15, k = idx >> 4;
        int grow = (r >> 2) * HH + j0 + (r & 3);   // gate*512 + j0 + unit
        float wv = W_hh[(size_t)grow * HH + k];
        W2[(k * ROWS + r) * 2 + 0] = wv;
        W2[(k * ROWS + r) * 2 + 1] = wv;
    }
    if (tid < ROWS) {
        int grow = (tid >> 2) * HH + j0 + (tid & 3);
        wih[tid]  = W_ih[grow];
        bsum[tid] = b_ih[grow] + b_hh[grow];
    }
    if (w == 14) x0s[lane] = x0[lane];           // x0 for t=0
    __syncthreads();

    float c_reg = 0.0f;     // epilogue threads (tid<128): unit w, batch lane
    float xnext = 0.0f;

    for (int t = 0; t < TT; ++t) {
        // Prefetch next step's x0 line early (hides the DRAM miss).
        if (w == 14 && t + 1 < TT) xnext = x0[(t + 1) * BB + lane];

        // ---- gate dots: all 16 rows per warp for its 32-k slice.
        // Sync is PER 4-k GROUP via sentinel validation: spin-reload a group
        // until none of its pairs is NANP. Prefetch distance 2 groups. ----
        unsigned long long acc[8] = {0, 0, 0, 0, 0, 0, 0, 0};
        if (t) {
            const unsigned long long* hq =
                (const unsigned long long*)(g_h + (size_t)(t - 1) * HB) + p;
            const float* wbase = W2 + kh * 16;
            unsigned long long hA[4], hB[4];
            #pragma unroll
            for (int i = 0; i < 4; ++i)
                ld_acq64(hA[i], hq + (size_t)(kbeg + i) * 16);
            #pragma unroll
            for (int i = 0; i < 4; ++i)
                ld_acq64(hB[i], hq + (size_t)(kbeg + 4 + i) * 16);
            #pragma unroll
            for (int g = 0; g < 8; ++g) {
                unsigned long long* hc = (g & 1) ? hB : hA;
                // Validate current group; respin-reload while any sentinel.
                for (;;) {
                    bool ok = (hc[0] != NANP) & (hc[1] != NANP)
                            & (hc[2] != NANP) & (hc[3] != NANP);
                    if (__all_sync(0xffffffffu, ok)) break;
                    #pragma unroll
                    for (int i = 0; i < 4; ++i)
                        ld_acq64(hc[i], hq + (size_t)(kbeg + g * 4 + i) * 16);
                }
                // Prefetch group g+2 into this buffer's sibling slot owner.
                unsigned long long* hn = (g & 1) ? hB : hA;  // same as hc
                #pragma unroll
                for (int i = 0; i < 4; ++i) {
                    const float* wk = wbase + (kbeg + g * 4 + i) * 32;
                    ulonglong2 w01 = *(const ulonglong2*)(wk);
                    ulonglong2 w23 = *(const ulonglong2*)(wk + 4);
                    ulonglong2 w45 = *(const ulonglong2*)(wk + 8);
                    ulonglong2 w67 = *(const ulonglong2*)(wk + 12);
                    fma2(acc[0], w01.x, hc[i]); fma2(acc[1], w01.y, hc[i]);
                    fma2(acc[2], w23.x, hc[i]); fma2(acc[3], w23.y, hc[i]);
                    fma2(acc[4], w45.x, hc[i]); fma2(acc[5], w45.y, hc[i]);
                    fma2(acc[6], w67.x, hc[i]); fma2(acc[7], w67.y, hc[i]);
                }
                // Reuse the just-consumed buffer for group g+2.
                if (g < 6) {
                    #pragma unroll
                    for (int i = 0; i < 4; ++i)
                        ld_acq64(hn[i],
                                 hq + (size_t)(kbeg + (g + 2) * 4 + i) * 16);
                }
            }
        }
        float* pb = part + (t & 1) * PART_FLOATS;   // double-buffered partials
        #pragma unroll
        for (int j = 0; j < 8; ++j)
            *(unsigned long long*)(pb + ((8 * kh + j) * NSEG + w) * 32 + 2 * p)
                = acc[j];
        __syncthreads();    // the ONLY CTA-wide barrier per step

        // Publish next x0 AFTER the barrier: epilogue(t-1) readers of this
        // buffer are provably done, epilogue(t) uses the other slot.
        if (w == 14) x0s[((t + 1) & 1) * 32 + lane] = xnext;

        // ---- LSTM cell epilogue: 128 threads = 4 units x 32 batches ----
        if (tid < 128) {
            const int u = w, b = lane;
            const float xv = x0s[(t & 1) * 32 + b];
            float gs[4];
            #pragma unroll
            for (int G = 0; G < 4; ++G) {
                const int r = G * 4 + u;
                const float* pr = pb + r * (NSEG * 32) + b;
                float s = 0.0f;
                #pragma unroll
                for (int ss = 0; ss < NSEG; ++ss) s += pr[ss * 32];
                gs[G] = s + fmaf(wih[r], xv, bsum[r]);
            }
            float ig = sig_f(gs[0]);
            float fg = sig_f(gs[1]);
            float gg = tanhf(gs[2]);
            float og = sig_f(gs[3]);
            c_reg = fmaf(fg, c_reg, ig * gg);
            float hv = og * tanhf(c_reg);
            // The store IS the publish (coalesced 128B; consumer pairs live
            // within one 32B sector -> appear atomically).
            g_h[(size_t)t * HB + (j0 + u) * BB + b] = hv;
        }
    }
}

// y[t][b] = x0 + b_lin + sum_j W_lin[j] * h[t][j][b]  — fully parallel over t,
// off the recurrence critical path. DRAM-bound: ~256MB read ≈ 35-40us.
__global__ void __launch_bounds__(256)
y_kernel(const float* __restrict__ x0,
         const float* __restrict__ W_lin,
         const float* __restrict__ b_lin,
         float* __restrict__ y)
{
    __shared__ float wl_s[HH];
    __shared__ float red[256];
    const int t = blockIdx.x, tid = threadIdx.x;
    for (int i = tid; i < HH; i += 256) wl_s[i] = W_lin[i];
    __syncthreads();
    const int b = tid & 31, jg = tid >> 5;
    const float* h = g_h + (size_t)t * HB;
    float acc = 0.0f;
    #pragma unroll 4
    for (int j = jg * 64; j < jg * 64 + 64; ++j)
        acc = fmaf(h[j * 32 + b], wl_s[j], acc);
    red[tid] = acc;
    __syncthreads();
    if (tid < 32) {
        float s = 0.0f;
        #pragma unroll
        for (int g = 0; g < 8; ++g) s += red[g * 32 + tid];
        y[t * BB + tid] = s + x0[t * BB + tid] + b_lin[0];
    }
}

extern "C" void kernel_launch(void* const* d_in, const int* in_sizes, int n_in,
                              void* d_out, int out_size)
{
    const float* x0    = (const float*)d_in[0];
    const float* W_ih  = (const float*)d_in[1];
    const float* W_hh  = (const float*)d_in[2];
    const float* b_ih  = (const float*)d_in[3];
    const float* b_hh  = (const float*)d_in[4];
    const float* W_lin = (const float*)d_in[5];
    const float* b_lin = (const float*)d_in[6];
    float* y = (float*)d_out;

    cudaFuncSetAttribute(lstm_kernel,
                         cudaFuncAttributeMaxDynamicSharedMemorySize, SMEM_BYTES);

    // NaN-fill 256MB of g_h: 16,777,216 ulonglong2 / 1024 = 16384 blocks.
    fill_kernel<<<16384, 1024>>>();
    lstm_kernel<<<NCTA, NTHR, SMEM_BYTES>>>(x0, W_ih, W_hh, b_ih, b_hh);
    y_kernel<<<TT, 256>>>(x0, W_lin, b_lin, y);
}

// round 10
// speedup vs baseline: 2.8843x; 2.8843x over previous
#include <cuda_runtime.h>
#include <math.h>

// Problem constants
#define TT    4096
#define BB    32
#define HH    512
#define HB    (HH * BB)            // 16384 floats per step
#define NCTA  128                  // persistent CTAs, all wave-1 resident
#define UNITS 4                    // hidden units per CTA
#define ROWS  16                   // gate rows per CTA (4 gates x 4 units)
#define NTHR  512                  // 16 warps
#define NSEG  16                   // k-segments per row (one per warp)
#define NGRP  16                   // barrier groups (8 CTAs each)
#define CTR_STRIDE 64              // 256B between counters -> distinct LTS lines

// Dynamic SMEM layout (floats)
#define PART_FLOATS (ROWS * NSEG * BB)          // 8192 floats = 32KB per buffer
#define SMEM_W2     (HH * ROWS * 2)             // duplicated weights: 64KB
#define SMEM_FLOATS (SMEM_W2 + 2 * PART_FLOATS + 128)
#define SMEM_BYTES  (SMEM_FLOATS * 4)           // ~131.5KB

// Inter-step hidden state [t][j][b] (b fastest). Distinct buffer per step
// => one-way producer/consumer sync, no anti-dependency.
__device__ float g_h[(size_t)TT * HB];   // 256 MB static scratch
// 16 cumulative group counters (group g = CTAs 8g..8g+7), padded 256B apart.
// PROVEN primitives only: red.release.gpu.add publish + ld.acquire.gpu poll.
// (R6/R7 store/cg-load flags hung; R9 per-element acquire sentinels 3x'd
// runtime. Coarse counter + plain cached data loads is the winner.)
__device__ __align__(256) unsigned g_ctr16[NGRP * CTR_STRIDE];

__global__ void init_kernel() { g_ctr16[threadIdx.x] = 0u; }  // 1024 threads

// Packed f32x2 FMA (Blackwell packed fp32 pipe).
__device__ __forceinline__ void fma2(unsigned long long& d,
                                     unsigned long long a,
                                     unsigned long long b) {
    asm("fma.rn.f32x2 %0, %1, %2, %0;" : "+l"(d) : "l"(a), "l"(b));
}

// Sigmoid via __expf is safe (R2/R4/R5/R8 evidence). tanh MUST stay accurate
// tanhf (R3: approx tanh -> rel_err 7e-4, too close to the 1e-3 gate).
__device__ __forceinline__ float sig_f(float x) {
    return __fdividef(1.0f, 1.0f + __expf(-x));
}

__global__ void __launch_bounds__(NTHR)   // no min-blocks: allow 128 regs
lstm_kernel(const float* __restrict__ x0,     // (T,B,1)
            const float* __restrict__ W_ih,   // (4H,1)
            const float* __restrict__ W_hh,   // (4H,H) row-major
            const float* __restrict__ b_ih,   // (4H)
            const float* __restrict__ b_hh)   // (4H)
{
    extern __shared__ float sm[];
    float* W2   = sm;                        // [k][r] duplicated pairs
    float* part = sm + SMEM_W2;              // 2 x [r][seg][b]
    float* x0s  = part + 2 * PART_FLOATS;    // 2 x 32 (double-buffered)
    float* wih  = x0s + 64;                  // 16
    float* bsum = wih + 16;                  // 16

    const int tid  = threadIdx.x;
    const int lane = tid & 31;
    const int w    = tid >> 5;           // warp 0..15 = k-segment
    const int kh   = lane >> 4;          // row-half: rows 8*kh .. 8*kh+7
    const int p    = lane & 15;          // batch pair -> batches 2p, 2p+1
    const int kbeg = w * 32;             // 32 k's per warp
    const int j0   = blockIdx.x * UNITS;
    // Counter this warp CONSUMES: group producing units [32w, 32w+32).
    const unsigned* cons_ctr = g_ctr16 + w * CTR_STRIDE;
    // Counter this CTA PRODUCES into: group blockIdx.x>>3.
    unsigned* prod_ctr = g_ctr16 + (blockIdx.x >> 3) * CTR_STRIDE;

    // Stage W_hh slice, k-major, duplicated pairs: W2[(k*16+r)*2 + {0,1}] = w.
    for (int idx = tid; idx < ROWS * HH; idx += NTHR) {
        int r = idx & 15, k = idx >> 4;
        int grow = (r >> 2) * HH + j0 + (r & 3);   // gate*512 + j0 + unit
        float wv = W_hh[(size_t)grow * HH + k];
        W2[(k * ROWS + r) * 2 + 0] = wv;
        W2[(k * ROWS + r) * 2 + 1] = wv;
    }
    if (tid < ROWS) {
        int grow = (tid >> 2) * HH + j0 + (tid & 3);
        wih[tid]  = W_ih[grow];
        bsum[tid] = b_ih[grow] + b_hh[grow];
    }
    if (w == 14) x0s[lane] = x0[lane];           // x0 for t=0
    __syncthreads();

    float c_reg = 0.0f;     // epilogue threads (tid<128): unit w, batch lane
    float xnext = 0.0f;

    for (int t = 0; t < TT; ++t) {
        // Prefetch next step's x0 line BEFORE the wait (hides the DRAM miss).
        if (w == 14 && t + 1 < TT) xnext = x0[(t + 1) * BB + lane];

        // ---- per-warp group wait (proven R8 primitive) ----
        if (t) {
            unsigned v;
            const unsigned tgt = 32u * (unsigned)t;
            do {
                asm volatile("ld.acquire.gpu.global.u32 %0, [%1];"
                             : "=r"(v) : "l"(cons_ctr) : "memory");
            } while (v < tgt);
        }

        // ---- gate dots: all 16 rows per warp for its 32-k slice.
        // ALL 32 h loads issued up front (MLP=32 -> ONE ~300cyc L2 flight)
        // into registers, then 416 stall-free LDS/FFMA2 instructions.
        unsigned long long acc[8] = {0, 0, 0, 0, 0, 0, 0, 0};
        if (t) {
            const unsigned long long* hq =
                (const unsigned long long*)(g_h + (size_t)(t - 1) * HB)
                + (size_t)kbeg * 16 + p;
            unsigned long long hp[32];
            #pragma unroll
            for (int i = 0; i < 32; ++i) hp[i] = hq[(size_t)i * 16];
            const float* wbase = W2 + (kbeg * 32) + kh * 16;
            #pragma unroll
            for (int k = 0; k < 32; ++k) {
                const float* wk = wbase + k * 32;
                ulonglong2 w01 = *(const ulonglong2*)(wk);
                ulonglong2 w23 = *(const ulonglong2*)(wk + 4);
                ulonglong2 w45 = *(const ulonglong2*)(wk + 8);
                ulonglong2 w67 = *(const ulonglong2*)(wk + 12);
                fma2(acc[0], w01.x, hp[k]); fma2(acc[1], w01.y, hp[k]);
                fma2(acc[2], w23.x, hp[k]); fma2(acc[3], w23.y, hp[k]);
                fma2(acc[4], w45.x, hp[k]); fma2(acc[5], w45.y, hp[k]);
                fma2(acc[6], w67.x, hp[k]); fma2(acc[7], w67.y, hp[k]);
            }
        }
        float* pb = part + (t & 1) * PART_FLOATS;   // double-buffered partials
        #pragma unroll
        for (int j = 0; j < 8; ++j)
            *(unsigned long long*)(pb + ((8 * kh + j) * NSEG + w) * 32 + 2 * p)
                = acc[j];
        __syncthreads();    // the ONLY CTA-wide barrier per step

        // Publish next x0 AFTER the barrier: epilogue(t-1) readers of this
        // buffer are provably done (flag chain), epilogue(t) uses the other.
        if (w == 14) x0s[((t + 1) & 1) * 32 + lane] = xnext;

        // ---- LSTM cell epilogue: 128 threads = 4 units x 32 batches ----
        if (tid < 128) {
            const int u = w, b = lane;
            const float xv = x0s[(t & 1) * 32 + b];
            float gs[4];
            #pragma unroll
            for (int G = 0; G < 4; ++G) {
                const int r = G * 4 + u;
                const float* pr = pb + r * (NSEG * 32) + b;
                float s = 0.0f;
                #pragma unroll
                for (int ss = 0; ss < NSEG; ++ss) s += pr[ss * 32];
                gs[G] = s + fmaf(wih[r], xv, bsum[r]);
            }
            float ig = sig_f(gs[0]);
            float fg = sig_f(gs[1]);
            float gg = tanhf(gs[2]);
            float og = sig_f(gs[3]);
            c_reg = fmaf(fg, c_reg, ig * gg);
            float hv = og * tanhf(c_reg);
            g_h[(size_t)t * HB + (j0 + u) * BB + b] = hv;

            // Per-warp publish: this warp's 32 h-STGs ordered into lane 0 by
            // __syncwarp, then ONE release-RED (32 REDs/counter/step).
            __syncwarp();
            if (b == 0)
                asm volatile("red.release.gpu.global.add.u32 [%0], 1;"
                             :: "l"(prod_ctr) : "memory");
        }
    }
}

// y[t][b] = x0 + b_lin + sum_j W_lin[j] * h[t][j][b]  — fully parallel over t,
// off the recurrence critical path. DRAM-bound: ~256MB read ≈ 35-40us.
__global__ void __launch_bounds__(256)
y_kernel(const float* __restrict__ x0,
         const float* __restrict__ W_lin,
         const float* __restrict__ b_lin,
         float* __restrict__ y)
{
    __shared__ float wl_s[HH];
    __shared__ float red[256];
    const int t = blockIdx.x, tid = threadIdx.x;
    for (int i = tid; i < HH; i += 256) wl_s[i] = W_lin[i];
    __syncthreads();
    const int b = tid & 31, jg = tid >> 5;
    const float* h = g_h + (size_t)t * HB;
    float acc = 0.0f;
    #pragma unroll 4
    for (int j = jg * 64; j < jg * 64 + 64; ++j)
        acc = fmaf(h[j * 32 + b], wl_s[j], acc);
    red[tid] = acc;
    __syncthreads();
    if (tid < 32) {
        float s = 0.0f;
        #pragma unroll
        for (int g = 0; g < 8; ++g) s += red[g * 32 + tid];
        y[t * BB + tid] = s + x0[t * BB + tid] + b_lin[0];
    }
}

extern "C" void kernel_launch(void* const* d_in, const int* in_sizes, int n_in,
                              void* d_out, int out_size)
{
    const float* x0    = (const float*)d_in[0];
    const float* W_ih  = (const float*)d_in[1];
    const float* W_hh  = (const float*)d_in[2];
    const float* b_ih  = (const float*)d_in[3];
    const float* b_hh  = (const float*)d_in[4];
    const float* W_lin = (const float*)d_in[5];
    const float* b_lin = (const float*)d_in[6];
    float* y = (float*)d_out;

    cudaFuncSetAttribute(lstm_kernel,
                         cudaFuncAttributeMaxDynamicSharedMemorySize, SMEM_BYTES);

    init_kernel<<<1, NGRP * CTR_STRIDE>>>();
    lstm_kernel<<<NCTA, NTHR, SMEM_BYTES>>>(x0, W_ih, W_hh, b_ih, b_hh);
    y_kernel<<<TT, 256>>>(x0, W_lin, b_lin, y);
}